// round 10
// baseline (speedup 1.0000x reference)
#include <cuda_runtime.h>
#include <cstdint>

// Problem constants
#define NB   32      // batch
#define CI   256     // in channels
#define CO   256     // out channels
#define HH   56
#define WW   56
#define HWSZ (HH*WW)       // 3136
#define CW   8             // 256 ch / 32 bits
#define NTAP 9

// Scratch (device globals; no allocation allowed)
__device__ unsigned g_Apk[NB * CW * HWSZ];      // packed activations [n][cw][h][w]
__device__ unsigned g_Wpk[CO * NTAP * CW];      // packed weights    [o][tap][cw]
__device__ int      g_PW [CO * NTAP];           // per (o,tap) popcount of weight bits

// ---------------------------------------------------------------------------
__device__ __forceinline__ unsigned lop3_96(unsigned a, unsigned b, unsigned c) {
    unsigned r;
    asm("lop3.b32 %0, %1, %2, %3, 0x96;" : "=r"(r) : "r"(a), "r"(b), "r"(c));
    return r;   // a ^ b ^ c
}
__device__ __forceinline__ unsigned lop3_e8(unsigned a, unsigned b, unsigned c) {
    unsigned r;
    asm("lop3.b32 %0, %1, %2, %3, 0xE8;" : "=r"(r) : "r"(a), "r"(b), "r"(c));
    return r;   // majority(a,b,c)
}
// carry-save adder: 2*h + l == a + b + c (bitwise)
#define CSA(h, l, a, b, c) do { unsigned _x=(a),_y=(b),_z=(c); \
    (h) = lop3_e8(_x,_y,_z); (l) = lop3_96(_x,_y,_z); } while (0)

// ---------------------------------------------------------------------------
// Pack activations: bit c set iff x[n][cw*32+c][h][w] >= 0
__global__ void pack_x_kernel(const float* __restrict__ x) {
    int idx = blockIdx.x * blockDim.x + threadIdx.x;
    if (idx >= NB * CW * HWSZ) return;
    int hw = idx % HWSZ;
    int t  = idx / HWSZ;
    int cw = t % CW;
    int n  = t / CW;
    const float* xp = x + ((size_t)(n * CI + cw * 32)) * HWSZ + hw;
    unsigned bits = 0;
#pragma unroll
    for (int c = 0; c < 32; c++) {
        bits |= (xp[(size_t)c * HWSZ] >= 0.0f ? 1u : 0u) << c;
    }
    g_Apk[idx] = bits;
}

// Pack weights: word (o,tap,cw); bit c set iff M[o][cw*32+c][tap] >= 0
__global__ void pack_w_kernel(const float* __restrict__ M) {
    int idx = blockIdx.x * blockDim.x + threadIdx.x;
    if (idx >= CO * NTAP * CW) return;
    int cw  = idx % CW;
    int t   = idx / CW;
    int tap = t % NTAP;
    int o   = t / NTAP;
    unsigned bits = 0;
#pragma unroll
    for (int c = 0; c < 32; c++) {
        float v = M[((size_t)(o * CI + cw * 32 + c)) * NTAP + tap];
        bits |= (v >= 0.0f ? 1u : 0u) << c;
    }
    g_Wpk[idx] = bits;
}

// Per (o,tap) total weight popcount (for border correction)
__global__ void pw_kernel() {
    int idx = blockIdx.x * blockDim.x + threadIdx.x;
    if (idx >= CO * NTAP) return;
    int s = 0;
#pragma unroll
    for (int cw = 0; cw < CW; cw++) s += __popc(g_Wpk[idx * CW + cw]);
    g_PW[idx] = s;
}

// ---------------------------------------------------------------------------
// Main conv. grid = (HH/TH, NB, NZ); block: 4-row tile, 64 o-channels.
// Harley-Seal CSA popcount; A tile as two uint4 planes (conflict-free).
// 6 blocks/SM (reg cap 48): 42 warps resident, 2.02 clean waves.
#define TH  4
#define OG  4                  // o-channels processed concurrently (CSA state)
#define NZ  4                  // grid.z split of output channels
#define OPB (CO / NZ)          // 64 o-channels per block
#define NTHREADS (WW * TH)     // 224

__global__ __launch_bounds__(NTHREADS, 6)
void bconv_kernel(const float* __restrict__ alpha, float* __restrict__ out) {
    __shared__ __align__(16) uint4 Asm0[TH + 2][WW + 2];         // 9,280 B
    __shared__ __align__(16) uint4 Asm1[TH + 2][WW + 2];         // 9,280 B
    __shared__ __align__(16) unsigned Wsm[OPB][NTAP][CW];        // 18,432 B
    __shared__ int   PWsm[OPB][NTAP];                            //  2,304 B
    __shared__ float Alp[OPB];                                   //    256 B

    const int tid    = threadIdx.x;
    const int h0     = blockIdx.x * TH;
    const int n      = blockIdx.y;
    const int obase0 = blockIdx.z * OPB;

    // --- stage activation tile (zero-padded), vectorized per plane ---
    const int SITES = (TH + 2) * (WW + 2);          // 348
    for (int i = tid; i < 2 * SITES; i += NTHREADS) {
        int u   = i / SITES;                        // plane: ch words 4u..4u+3
        int s   = i % SITES;
        int row = s / (WW + 2);
        int col = s % (WW + 2);
        int gh  = h0 - 1 + row;
        int gw  = col - 1;
        uint4 v = make_uint4(0, 0, 0, 0);
        if (gh >= 0 && gh < HH && gw >= 0 && gw < WW) {
            const unsigned* gp = &g_Apk[(n * CW + u * 4) * HWSZ + gh * WW + gw];
            v.x = gp[0];
            v.y = gp[HWSZ];
            v.z = gp[2 * HWSZ];
            v.w = gp[3 * HWSZ];
        }
        if (u == 0) Asm0[row][col] = v; else Asm1[row][col] = v;
    }
    // --- stage weights for this block's 64 o-channels ---
    for (int i = tid; i < OPB * NTAP * CW; i += NTHREADS)
        ((unsigned*)Wsm)[i] = g_Wpk[obase0 * NTAP * CW + i];
    for (int i = tid; i < OPB * NTAP; i += NTHREADS)
        ((int*)PWsm)[i] = g_PW[obase0 * NTAP + i];
    for (int i = tid; i < OPB; i += NTHREADS)
        Alp[i] = alpha[obase0 + i];

    __syncthreads();   // the ONLY barrier in this kernel

    const int tx = tid % WW;        // w
    const int ty = tid / WW;        // 0..3
    const int h  = h0 + ty;
    const int w  = tx;

    const int nrows = 1 + (h > 0) + (h < HH - 1);
    const int ncols = 1 + (w > 0) + (w < WW - 1);
    const int nv    = nrows * ncols;
    const int hw    = h * WW + w;
    const bool border = (nv != 9);

#pragma unroll 1
    for (int og = 0; og < OPB / OG; og++) {
        const int ob = og * OG;

        unsigned ones[OG], twos[OG], fours[OG];
        int acc8[OG];
#pragma unroll
        for (int j = 0; j < OG; j++) { ones[j] = 0; twos[j] = 0; fours[j] = 0; acc8[j] = 0; }

#pragma unroll
        for (int tap = 0; tap < NTAP; tap++) {
            const int dy = tap / 3;
            const int dx = tap - dy * 3;
            const uint4 a0 = Asm0[ty + dy][tx + dx];
            const uint4 a1 = Asm1[ty + dy][tx + dx];
#pragma unroll
            for (int j = 0; j < OG; j++) {
                const uint4* wp = (const uint4*)&Wsm[ob + j][tap][0];
                const uint4 w0 = wp[0];
                const uint4 w1 = wp[1];
                const unsigned d0 = a0.x ^ w0.x, d1 = a0.y ^ w0.y;
                const unsigned d2 = a0.z ^ w0.z, d3 = a0.w ^ w0.w;
                const unsigned d4 = a1.x ^ w1.x, d5 = a1.y ^ w1.y;
                const unsigned d6 = a1.z ^ w1.z, d7 = a1.w ^ w1.w;
                unsigned ta, tb, fa, fb, eig;
                CSA(ta, ones[j], ones[j], d0, d1);
                CSA(tb, ones[j], ones[j], d2, d3);
                CSA(fa, twos[j], twos[j], ta, tb);
                CSA(ta, ones[j], ones[j], d4, d5);
                CSA(tb, ones[j], ones[j], d6, d7);
                CSA(fb, twos[j], twos[j], ta, tb);
                CSA(eig, fours[j], fours[j], fa, fb);
                acc8[j] += __popc(eig);
            }
        }

        // finalize + write outputs (border correction only when needed)
#pragma unroll
        for (int j = 0; j < OG; j++) {
            const int o = ob + j;
            int acc = (acc8[j] << 3) + (__popc(fours[j]) << 2)
                    + (__popc(twos[j]) << 1) + __popc(ones[j]);
            int corr = 0;
            if (border) {
#pragma unroll
                for (int tap = 0; tap < NTAP; tap++) {
                    int dy = tap / 3 - 1, dx = tap % 3 - 1;
                    int gh = h + dy, gw = w + dx;
                    if (!(gh >= 0 && gh < HH && gw >= 0 && gw < WW))
                        corr += PWsm[o][tap];
                }
            }
            out[((size_t)(n * CO + obase0 + o)) * HWSZ + hw] =
                Alp[o] * (float)(nv * 256 - 2 * acc + 2 * corr);
        }
    }
}

// ---------------------------------------------------------------------------
extern "C" void kernel_launch(void* const* d_in, const int* in_sizes, int n_in,
                              void* d_out, int out_size) {
    const float* x     = (const float*)d_in[0];   // (32,256,56,56)
    const float* M     = (const float*)d_in[1];   // (256,256,3,3)
    const float* alpha = (const float*)d_in[2];   // (256,1,1)
    float* out         = (float*)d_out;           // (32,256,56,56)

    {
        int total = NB * CW * HWSZ;               // 802816
        pack_x_kernel<<<(total + 255) / 256, 256>>>(x);
    }
    {
        int total = CO * NTAP * CW;               // 18432
        pack_w_kernel<<<(total + 127) / 128, 128>>>(M);
    }
    {
        int total = CO * NTAP;                    // 2304
        pw_kernel<<<(total + 127) / 128, 128>>>();
    }
    {
        dim3 grid(HH / TH, NB, NZ);               // (14, 32, 4) = 1792 blocks
        bconv_kernel<<<grid, NTHREADS>>>(alpha, out);
    }
}

// round 11
// speedup vs baseline: 1.2116x; 1.2116x over previous
#include <cuda_runtime.h>
#include <cstdint>

// Problem constants
#define NB   32      // batch
#define CI   256     // in channels
#define CO   256     // out channels
#define HH   56
#define WW   56
#define HWSZ (HH*WW)       // 3136
#define CW   8             // 256 ch / 32 bits
#define NTAP 9

// Scratch (device globals; no allocation allowed)
__device__ unsigned g_Apk[NB * CW * HWSZ];      // packed activations [n][cw][h][w]
__device__ unsigned g_Wpk[CO * NTAP * CW];      // packed weights    [o][tap][cw]
__device__ int      g_PW [CO * NTAP];           // per (o,tap) popcount of weight bits

// ---------------------------------------------------------------------------
__device__ __forceinline__ unsigned lop3_96(unsigned a, unsigned b, unsigned c) {
    unsigned r;
    asm("lop3.b32 %0, %1, %2, %3, 0x96;" : "=r"(r) : "r"(a), "r"(b), "r"(c));
    return r;   // a ^ b ^ c
}
__device__ __forceinline__ unsigned lop3_e8(unsigned a, unsigned b, unsigned c) {
    unsigned r;
    asm("lop3.b32 %0, %1, %2, %3, 0xE8;" : "=r"(r) : "r"(a), "r"(b), "r"(c));
    return r;   // majority(a,b,c)
}
// carry-save adder: 2*h + l == a + b + c (bitwise popcount identity)
#define CSA(h, l, a, b, c) do { unsigned _x=(a),_y=(b),_z=(c); \
    (h) = lop3_e8(_x,_y,_z); (l) = lop3_96(_x,_y,_z); } while (0)

// ---------------------------------------------------------------------------
// Pack activations: bit c set iff x[n][cw*32+c][h][w] >= 0
__global__ void pack_x_kernel(const float* __restrict__ x) {
    int idx = blockIdx.x * blockDim.x + threadIdx.x;
    if (idx >= NB * CW * HWSZ) return;
    int hw = idx % HWSZ;
    int t  = idx / HWSZ;
    int cw = t % CW;
    int n  = t / CW;
    const float* xp = x + ((size_t)(n * CI + cw * 32)) * HWSZ + hw;
    unsigned bits = 0;
#pragma unroll
    for (int c = 0; c < 32; c++) {
        bits |= (xp[(size_t)c * HWSZ] >= 0.0f ? 1u : 0u) << c;
    }
    g_Apk[idx] = bits;
}

// Pack weights: word (o,tap,cw); bit c set iff M[o][cw*32+c][tap] >= 0
__global__ void pack_w_kernel(const float* __restrict__ M) {
    int idx = blockIdx.x * blockDim.x + threadIdx.x;
    if (idx >= CO * NTAP * CW) return;
    int cw  = idx % CW;
    int t   = idx / CW;
    int tap = t % NTAP;
    int o   = t / NTAP;
    unsigned bits = 0;
#pragma unroll
    for (int c = 0; c < 32; c++) {
        float v = M[((size_t)(o * CI + cw * 32 + c)) * NTAP + tap];
        bits |= (v >= 0.0f ? 1u : 0u) << c;
    }
    g_Wpk[idx] = bits;
}

// Per (o,tap) total weight popcount (for border correction)
__global__ void pw_kernel() {
    int idx = blockIdx.x * blockDim.x + threadIdx.x;
    if (idx >= CO * NTAP) return;
    int s = 0;
#pragma unroll
    for (int cw = 0; cw < CW; cw++) s += __popc(g_Wpk[idx * CW + cw]);
    g_PW[idx] = s;
}

// ---------------------------------------------------------------------------
// Main conv. grid = (HH/TH, NB, NZ); block: 4-row tile, 64 o-channels.
// Shallow CSA (to 'twos' level) + POPC-pipe offload:
//   per tap-o: 4 CSAs (8 LOP3) emit four twos-words -> 4 POPC on the popc
//   pipe, only 'ones' parity carried across taps.
//   acc = 2*acc2 + popc(ones_final)  (exact integer identity).
// alu ops/px-o: 207 -> ~165; popc 12 -> 37 (popc pipe stays non-binding).
#define TH  4
#define OG  4                  // o-channels processed concurrently
#define NZ  4                  // grid.z split of output channels
#define OPB (CO / NZ)          // 64 o-channels per block
#define NTHREADS (WW * TH)     // 224

__global__ __launch_bounds__(NTHREADS, 5)
void bconv_kernel(const float* __restrict__ alpha, float* __restrict__ out) {
    __shared__ __align__(16) uint4 Asm0[TH + 2][WW + 2];         // 9,280 B
    __shared__ __align__(16) uint4 Asm1[TH + 2][WW + 2];         // 9,280 B
    __shared__ __align__(16) unsigned Wsm[OPB][NTAP][CW];        // 18,432 B
    __shared__ int   PWsm[OPB][NTAP];                            //  2,304 B
    __shared__ float Alp[OPB];                                   //    256 B

    const int tid    = threadIdx.x;
    const int h0     = blockIdx.x * TH;
    const int n      = blockIdx.y;
    const int obase0 = blockIdx.z * OPB;

    // --- stage activation tile (zero-padded), vectorized per plane ---
    const int SITES = (TH + 2) * (WW + 2);          // 348
    for (int i = tid; i < 2 * SITES; i += NTHREADS) {
        int u   = i / SITES;                        // plane: ch words 4u..4u+3
        int s   = i % SITES;
        int row = s / (WW + 2);
        int col = s % (WW + 2);
        int gh  = h0 - 1 + row;
        int gw  = col - 1;
        uint4 v = make_uint4(0, 0, 0, 0);
        if (gh >= 0 && gh < HH && gw >= 0 && gw < WW) {
            const unsigned* gp = &g_Apk[(n * CW + u * 4) * HWSZ + gh * WW + gw];
            v.x = gp[0];
            v.y = gp[HWSZ];
            v.z = gp[2 * HWSZ];
            v.w = gp[3 * HWSZ];
        }
        if (u == 0) Asm0[row][col] = v; else Asm1[row][col] = v;
    }
    // --- stage weights for this block's 64 o-channels ---
    for (int i = tid; i < OPB * NTAP * CW; i += NTHREADS)
        ((unsigned*)Wsm)[i] = g_Wpk[obase0 * NTAP * CW + i];
    for (int i = tid; i < OPB * NTAP; i += NTHREADS)
        ((int*)PWsm)[i] = g_PW[obase0 * NTAP + i];
    for (int i = tid; i < OPB; i += NTHREADS)
        Alp[i] = alpha[obase0 + i];

    __syncthreads();   // the ONLY barrier in this kernel

    const int tx = tid % WW;        // w
    const int ty = tid / WW;        // 0..3
    const int h  = h0 + ty;
    const int w  = tx;

    const int nrows = 1 + (h > 0) + (h < HH - 1);
    const int ncols = 1 + (w > 0) + (w < WW - 1);
    const int nv    = nrows * ncols;
    const int hw    = h * WW + w;
    const bool border = (nv != 9);

#pragma unroll 1
    for (int og = 0; og < OPB / OG; og++) {
        const int ob = og * OG;

        unsigned ones[OG];
        int acc2[OG];
#pragma unroll
        for (int j = 0; j < OG; j++) { ones[j] = 0; acc2[j] = 0; }

#pragma unroll
        for (int tap = 0; tap < NTAP; tap++) {
            const int dy = tap / 3;
            const int dx = tap - dy * 3;
            const uint4 a0 = Asm0[ty + dy][tx + dx];
            const uint4 a1 = Asm1[ty + dy][tx + dx];
#pragma unroll
            for (int j = 0; j < OG; j++) {
                const uint4* wp = (const uint4*)&Wsm[ob + j][tap][0];
                const uint4 w0 = wp[0];
                const uint4 w1 = wp[1];
                const unsigned d0 = a0.x ^ w0.x, d1 = a0.y ^ w0.y;
                const unsigned d2 = a0.z ^ w0.z, d3 = a0.w ^ w0.w;
                const unsigned d4 = a1.x ^ w1.x, d5 = a1.y ^ w1.y;
                const unsigned d6 = a1.z ^ w1.z, d7 = a1.w ^ w1.w;
                unsigned ta, tb, tc, td;
                CSA(ta, ones[j], ones[j], d0, d1);
                CSA(tb, ones[j], ones[j], d2, d3);
                CSA(tc, ones[j], ones[j], d4, d5);
                CSA(td, ones[j], ones[j], d6, d7);
                acc2[j] += (__popc(ta) + __popc(tb)) + (__popc(tc) + __popc(td));
            }
        }

        // finalize + write outputs (border correction only when needed)
#pragma unroll
        for (int j = 0; j < OG; j++) {
            const int o = ob + j;
            int acc = (acc2[j] << 1) + __popc(ones[j]);
            int corr = 0;
            if (border) {
#pragma unroll
                for (int tap = 0; tap < NTAP; tap++) {
                    int dy = tap / 3 - 1, dx = tap % 3 - 1;
                    int gh = h + dy, gw = w + dx;
                    if (!(gh >= 0 && gh < HH && gw >= 0 && gw < WW))
                        corr += PWsm[o][tap];
                }
            }
            out[((size_t)(n * CO + obase0 + o)) * HWSZ + hw] =
                Alp[o] * (float)(nv * 256 - 2 * acc + 2 * corr);
        }
    }
}

// ---------------------------------------------------------------------------
extern "C" void kernel_launch(void* const* d_in, const int* in_sizes, int n_in,
                              void* d_out, int out_size) {
    const float* x     = (const float*)d_in[0];   // (32,256,56,56)
    const float* M     = (const float*)d_in[1];   // (256,256,3,3)
    const float* alpha = (const float*)d_in[2];   // (256,1,1)
    float* out         = (float*)d_out;           // (32,256,56,56)

    {
        int total = NB * CW * HWSZ;               // 802816
        pack_x_kernel<<<(total + 255) / 256, 256>>>(x);
    }
    {
        int total = CO * NTAP * CW;               // 18432
        pack_w_kernel<<<(total + 127) / 128, 128>>>(M);
    }
    {
        int total = CO * NTAP;                    // 2304
        pw_kernel<<<(total + 127) / 128, 128>>>();
    }
    {
        dim3 grid(HH / TH, NB, NZ);               // (14, 32, 4) = 1792 blocks
        bconv_kernel<<<grid, NTHREADS>>>(alpha, out);
    }
}